// round 16
// baseline (speedup 1.0000x reference)
#include <cuda_runtime.h>
#include <cuda_fp16.h>
#include <math.h>
#include <stdint.h>

#define Bn   128
#define Tn   256
#define DIN  512
#define Hn   1024
#define G4   4096
#define BRn  256

#define NCH0 24            // K64 chunks, layer0 (h0:16, X:8)
#define NCH1 32            // K64 chunks, layer1 (h0:16, h1:16)
#define NST0 12            // K128 stages, layer0
#define NST1 16            // K128 stages, layer1

#define NSTAGE 4
#define NPRE   3                              // stages issued ahead / prefetched
#define ST_W   16384
#define STAGEB 32768
#define BLK    16384                          // A-block stride in packed arrays
#define SMEM_STAGES (NSTAGE * STAGEB)         // 131072
#define SMEM_SG  SMEM_STAGES                  // float Sg[2][64][68] = 34816
#define SMEM_CS  (SMEM_SG + 34816)            // c-state 2*64*16 f32 = 8192
#define SMEM_MB  (SMEM_CS + 8192)
#define SMEM_BYTES (SMEM_MB + 64)             // 174144
#define NCTA 128

#define SWZ128(o) ((o) ^ (((o) >> 3) & 0x70))

// ---------------------------------------------------------------------------
// Device scratch — pre-swizzled blocks
// ---------------------------------------------------------------------------
__device__ __align__(1024) unsigned char g_Xp[(size_t)Tn * 8 * 16384];      // [t*8+kc][swz(b*128+col*2)]
__device__ __align__(1024) unsigned char g_W0p[(size_t)64 * NCH0 * 8192];   // [nt*NCH0+kc][swz(r*128+col*2)]
__device__ __align__(1024) unsigned char g_W1p[(size_t)64 * NCH1 * 8192];
__device__ __align__(1024) unsigned char g_h0p[2][16 * 16384];              // [jc][swz(b*128+jl*2)]
__device__ __align__(1024) unsigned char g_h1p[2][16 * 16384];
__device__ float g_b0p[G4], g_b1p[G4];
__device__ unsigned int g_bar;

// ---------------------------------------------------------------------------
// Primitives
// ---------------------------------------------------------------------------
__device__ __forceinline__ uint32_t smem_u32(const void* p) {
    uint32_t a;
    asm("{ .reg .u64 t; cvta.to.shared.u64 t, %1; cvt.u32.u64 %0, t; }"
        : "=r"(a) : "l"(p));
    return a;
}
__device__ __forceinline__ void ldsm4(uint32_t* r, uint32_t addr) {
    asm volatile("ldmatrix.sync.aligned.m8n8.x4.shared.b16 {%0,%1,%2,%3}, [%4];"
                 : "=r"(r[0]), "=r"(r[1]), "=r"(r[2]), "=r"(r[3]) : "r"(addr));
}
__device__ __forceinline__ void hmma16(float* d, const uint32_t* a, uint32_t b0, uint32_t b1) {
    asm volatile("mma.sync.aligned.m16n8k16.row.col.f32.f16.f16.f32 "
                 "{%0,%1,%2,%3}, {%4,%5,%6,%7}, {%8,%9}, {%0,%1,%2,%3};"
                 : "+f"(d[0]), "+f"(d[1]), "+f"(d[2]), "+f"(d[3])
                 : "r"(a[0]), "r"(a[1]), "r"(a[2]), "r"(a[3]), "r"(b0), "r"(b1));
}
__device__ __forceinline__ void bulk_g2s(uint32_t dst, const void* src, uint32_t bytes,
                                         uint32_t mbar) {
    asm volatile("cp.async.bulk.shared::cta.global.mbarrier::complete_tx::bytes "
                 "[%0], [%1], %2, [%3];"
                 :: "r"(dst), "l"(src), "r"(bytes), "r"(mbar) : "memory");
}
#define MBARRIER_INIT(mb, c) \
    asm volatile("mbarrier.init.shared.b64 [%0], %1;" :: "r"((uint32_t)(mb)), "r"((uint32_t)(c)) : "memory")
#define MBARRIER_EXPECT_TX(mb, tx) \
    asm volatile("mbarrier.arrive.expect_tx.shared.b64 _, [%0], %1;" :: "r"((uint32_t)(mb)), "r"((uint32_t)(tx)) : "memory")
#define FENCE_PROXY_ASYNC() asm volatile("fence.proxy.async.shared::cta;" ::: "memory")
#define MBARRIER_WAIT_PARITY(mb, par) do {                                         \
    uint32_t _mb = (uint32_t)(mb); uint32_t _p = (uint32_t)(par); uint32_t _d;     \
    asm volatile("{\n\t.reg .pred p;\n\t"                                          \
        "mbarrier.try_wait.parity.acquire.cta.shared::cta.b64 p, [%1], %2;\n\t"    \
        "selp.b32 %0, 1, 0, p;\n\t}" : "=r"(_d) : "r"(_mb), "r"(_p) : "memory");   \
    if (!_d) {                                                                     \
        asm volatile("{\n\t.reg .pred P1;\n\t"                                     \
            "WL_%=:\n\t"                                                           \
            "mbarrier.try_wait.parity.acquire.cta.shared::cta.b64 P1, [%0], %1, 0x989680;\n\t" \
            "@P1 bra.uni WD_%=;\n\t"                                               \
            "bra.uni WL_%=;\n\t"                                                   \
            "WD_%=:\n\t}" :: "r"(_mb), "r"(_p) : "memory");                        \
    }                                                                              \
} while (0)

__device__ __forceinline__ float fsigmoid(float x) {
    return __fdividef(1.f, 1.f + __expf(-x));
}
__device__ __forceinline__ float ftanh_(float x) {
    return 2.f * __fdividef(1.f, 1.f + __expf(-2.f * x)) - 1.f;
}

// ---------------------------------------------------------------------------
// Job descriptor (stage = 2 K64 chunks)
// ---------------------------------------------------------------------------
struct Job {
    const unsigned char *A0, *A1;   // A block bases (+mo), stride BLK; switch at K-chunk 16
    const unsigned char *Wb;        // W block base (CTA's ntile), stride 8192, contiguous
    int nst;                        // stages (K128)
    const float* biasp;
    float* cseg;
    unsigned char* hout;            // packed h buffer base
};

// W half of a stage: expect_tx(32KB) + one 16KB W bulk.  tid0 only.
__device__ __forceinline__ void issue_W_stage(const Job* jobs, int nst0, int sc,
                                              unsigned g, uint32_t sb, uint32_t mb) {
    const Job& J = jobs[sc >= nst0 ? 1 : 0];
    int ls  = (sc >= nst0) ? sc - nst0 : sc;
    int kc2 = ls * 2;
    uint32_t s    = g % NSTAGE;
    uint32_t mbar = mb + s * 8;
    MBARRIER_EXPECT_TX(mbar, 32768u);
    bulk_g2s(sb + s * STAGEB + ST_W, J.Wb + (size_t)kc2 * 8192, 16384u, mbar);
}
// A half of a stage: two 8KB bulks (blocks are BLK apart).  tid0 only.
__device__ __forceinline__ void issue_A_stage(const Job* jobs, int nst0, int sc,
                                              unsigned g, uint32_t sb, uint32_t mb) {
    const Job& J = jobs[sc >= nst0 ? 1 : 0];
    int ls  = (sc >= nst0) ? sc - nst0 : sc;
    int kc2 = ls * 2;
    const unsigned char* Ab = (kc2 < 16) ? J.A0 + (size_t)kc2 * BLK
                                         : J.A1 + (size_t)(kc2 - 16) * BLK;
    uint32_t s    = g % NSTAGE;
    uint32_t mbar = mb + s * 8;
    uint32_t dst  = sb + s * STAGEB;
    bulk_g2s(dst,        Ab,       8192u, mbar);
    bulk_g2s(dst + 8192, Ab + BLK, 8192u, mbar);
}
__device__ __forceinline__ void issue_stage(const Job* jobs, int nst0, int sc,
                                            unsigned g, uint32_t sb, uint32_t mb) {
    issue_W_stage(jobs, nst0, sc, g, sb, mb);
    issue_A_stage(jobs, nst0, sc, g, sb, mb);
}

// One K=128 stage, K-split tiling: warp (wg, wm, wn) covers output rows
// [wm*32,+32) x cols [wn*32,+32), accumulating K-half wg of each K64 chunk.
__device__ __forceinline__ void mma_stage(uint32_t st, int wg, int wm, int wn, int lane,
                                          float acc[2][4][4]) {
#pragma unroll
    for (int sub = 0; sub < 2; sub++) {
        uint32_t sA = st + sub * 8192;
        uint32_t sW = st + ST_W + sub * 8192;
#pragma unroll
        for (int k16 = 0; k16 < 2; k16++) {
            int akb = (wg * 32 + k16 * 16 + (lane >> 4) * 8) * 2;
            uint32_t a[2][4];
#pragma unroll
            for (int mt = 0; mt < 2; mt++) {
                int arow = wm * 32 + mt * 16 + (lane & 15);
                ldsm4(a[mt], sA + SWZ128(arow * 128 + akb));
            }
#pragma unroll
            for (int nb = 0; nb < 2; nb++) {
                int brow = wn * 32 + nb * 16 + (lane & 15);
                uint32_t b[4];
                ldsm4(b, sW + SWZ128(brow * 128 + akb));
#pragma unroll
                for (int mt = 0; mt < 2; mt++) {
                    hmma16(acc[mt][nb * 2 + 0], a[mt], b[0], b[2]);
                    hmma16(acc[mt][nb * 2 + 1], a[mt], b[1], b[3]);
                }
            }
        }
    }
}

// acc -> Sg[wg] -> sum K-groups -> gates -> cell update -> packed h write.
__device__ __forceinline__ void epilogue_cell(
    char* smem, float acc[2][4][4], int wg, int wm, int wn, int lane, int tid,
    const Job& J, int m0, int p0)
{
    float (*Sg)[64][68] = (float(*)[64][68])(smem + SMEM_SG);
#pragma unroll
    for (int mt = 0; mt < 2; mt++)
#pragma unroll
        for (int nb = 0; nb < 2; nb++)
#pragma unroll
            for (int g = 0; g < 2; g++) {
                int f  = nb * 2 + g;
                int cc = wn * 32 + nb * 16 + g * 8 + (lane & 3) * 2;
                int rr = wm * 32 + mt * 16 + (lane >> 2);
                Sg[wg][rr][cc]         = acc[mt][f][0];
                Sg[wg][rr][cc + 1]     = acc[mt][f][1];
                Sg[wg][rr + 8][cc]     = acc[mt][f][2];
                Sg[wg][rr + 8][cc + 1] = acc[mt][f][3];
            }
    __syncthreads();
#pragma unroll
    for (int i = 0; i < 4; i++) {
        int lin = tid + i * 256;
        int m = lin >> 4, u = lin & 15;
        int b = m0 + m;
        int col = u * 4;
        float pi_ = Sg[0][m][col]     + Sg[1][m][col]     + J.biasp[p0 + col];
        float pf  = Sg[0][m][col + 1] + Sg[1][m][col + 1] + J.biasp[p0 + col + 1];
        float pg  = Sg[0][m][col + 2] + Sg[1][m][col + 2] + J.biasp[p0 + col + 2];
        float po  = Sg[0][m][col + 3] + Sg[1][m][col + 3] + J.biasp[p0 + col + 3];
        int ci = m * 16 + u;
        float co = J.cseg[ci];
        float ii = fsigmoid(pi_);
        float ff = fsigmoid(pf);
        float gg = ftanh_(pg);
        float oo = fsigmoid(po);
        float cn = ff * co + ii * gg;
        float h  = oo * ftanh_(cn);
        J.cseg[ci] = cn;
        int j = (p0 >> 2) + u;
        size_t off = (size_t)(j >> 6) * BLK + SWZ128(b * 128 + (j & 63) * 2);
        *(__half*)(J.hout + off) = __float2half(h);
    }
}

// ---------------------------------------------------------------------------
// Phase: up to 2 jobs; 4-deep stage ring, issue-ahead 3.
// preloaded: W+expect of stages gc..gc+NPRE-1 already issued pre-barrier.
// Reuse safety: issuing stage c+NPRE targets slot (c-1)%4, consumed in
// iteration c-1 and fenced by that iteration's trailing __syncthreads.
// ---------------------------------------------------------------------------
__device__ void phase_exec(const Job* jobs, int njobs, bool preloaded, unsigned& gcref,
                           char* smem, uint32_t sb, uint32_t mb,
                           int tid, int wg, int wm, int wn, int lane, int m0, int p0) {
    const int nst0 = jobs[0].nst;
    const int TOT = nst0 + (njobs > 1 ? jobs[1].nst : 0);
    const unsigned gc = gcref;
    float acc[2][4][4];
#pragma unroll
    for (int mt = 0; mt < 2; mt++)
#pragma unroll
        for (int r = 0; r < 4; r++)
#pragma unroll
            for (int c = 0; c < 4; c++) acc[mt][r][c] = 0.f;

    if (tid == 0) {
#pragma unroll
        for (int c = 0; c < NPRE; c++) {
            if (!preloaded) issue_W_stage(jobs, nst0, c, gc + c, sb, mb);
            issue_A_stage(jobs, nst0, c, gc + c, sb, mb);
        }
    }

    for (int c = 0; c < TOT; c++) {
        unsigned g = gc + c;
        uint32_t s = g % NSTAGE;
        MBARRIER_WAIT_PARITY(mb + s * 8, (g / NSTAGE) & 1);
        if (tid == 0 && c + NPRE < TOT)
            issue_stage(jobs, nst0, c + NPRE, g + NPRE, sb, mb);
        mma_stage(sb + s * STAGEB, wg, wm, wn, lane, acc);
        if (c == nst0 - 1) {
            epilogue_cell(smem, acc, wg, wm, wn, lane, tid, jobs[0], m0, p0);
#pragma unroll
            for (int mt = 0; mt < 2; mt++)
#pragma unroll
                for (int r = 0; r < 4; r++)
#pragma unroll
                    for (int cl = 0; cl < 4; cl++) acc[mt][r][cl] = 0.f;
        } else if (c == TOT - 1) {
            epilogue_cell(smem, acc, wg, wm, wn, lane, tid, jobs[1], m0, p0);
        }
        __syncthreads();
    }
    gcref = gc + TOT;
}

// Grid-wide barrier (tight spin)
__device__ __forceinline__ void grid_bar(unsigned target) {
    __syncthreads();
    if (threadIdx.x == 0) {
        __threadfence();
        atomicAdd(&g_bar, 1u);
        while (*(volatile unsigned int*)&g_bar < target) { }
        __threadfence();
    }
    __syncthreads();
}

// ---------------------------------------------------------------------------
// Prep kernels (pre-swizzled blocks)
// ---------------------------------------------------------------------------
__global__ void pack_X_kernel(const float* __restrict__ X) {
    size_t i = (size_t)blockIdx.x * blockDim.x + threadIdx.x;
    if (i >= (size_t)Bn * Tn * DIN) return;
    int d = (int)(i % DIN);
    size_t r = i / DIN;
    int t = (int)(r % Tn), b = (int)(r / Tn);
    int kc = d >> 6, col = d & 63;
    size_t off = (size_t)(t * 8 + kc) * BLK + SWZ128(b * 128 + col * 2);
    *(__half*)(g_Xp + off) = __float2half(X[i]);
}
__global__ void pack_w0_kernel(const float* __restrict__ Wih,
                               const float* __restrict__ Whh) {
    size_t i = (size_t)blockIdx.x * blockDim.x + threadIdx.x;
    if (i >= (size_t)G4 * 1536) return;
    int p = (int)(i / 1536), k = (int)(i % 1536);
    int j = p >> 2, g4 = p & 3;
    float v = (k < Hn) ? Whh[(size_t)(g4 * Hn + j) * Hn + k]
                       : Wih[(size_t)(g4 * Hn + j) * DIN + (k - Hn)];
    int nt = p >> 6, rr = p & 63, kc = k >> 6, col = k & 63;
    size_t off = (size_t)(nt * NCH0 + kc) * 8192 + SWZ128(rr * 128 + col * 2);
    *(__half*)(g_W0p + off) = __float2half(v);
}
__global__ void pack_w1_kernel(const float* __restrict__ Wih,
                               const float* __restrict__ Whh) {
    size_t i = (size_t)blockIdx.x * blockDim.x + threadIdx.x;
    if (i >= (size_t)G4 * 2048) return;
    int p = (int)(i / 2048), k = (int)(i % 2048);
    int j = p >> 2, g4 = p & 3;
    float v = (k < Hn) ? Wih[(size_t)(g4 * Hn + j) * Hn + k]
                       : Whh[(size_t)(g4 * Hn + j) * Hn + (k - Hn)];
    int nt = p >> 6, rr = p & 63, kc = k >> 6, col = k & 63;
    size_t off = (size_t)(nt * NCH1 + kc) * 8192 + SWZ128(rr * 128 + col * 2);
    *(__half*)(g_W1p + off) = __float2half(v);
}
__global__ void pack_bias_kernel(const float* __restrict__ bi0, const float* __restrict__ bh0,
                                 const float* __restrict__ bi1, const float* __restrict__ bh1) {
    int p = blockIdx.x * blockDim.x + threadIdx.x;
    if (p >= G4) return;
    int j = p >> 2, g = p & 3;
    g_b0p[p] = bi0[g * Hn + j] + bh0[g * Hn + j];
    g_b1p[p] = bi1[g * Hn + j] + bh1[g * Hn + j];
}
__global__ void init_state_kernel() {
    size_t i = (size_t)blockIdx.x * blockDim.x + threadIdx.x;
    if (i < (size_t)16 * 16384 / 4) {
        ((uint32_t*)g_h0p[0])[i] = 0; ((uint32_t*)g_h0p[1])[i] = 0;
        ((uint32_t*)g_h1p[0])[i] = 0; ((uint32_t*)g_h1p[1])[i] = 0;
    }
    if (i == 0) g_bar = 0u;
}

// ---------------------------------------------------------------------------
// Persistent LSTM: 128 CTAs; phase = {layer1(t), layer0(t+1)}; 1 barrier/phase;
// K128 stages; K-split 32x32 warp tiles; 4-deep ring; W prefetch across barrier.
// ---------------------------------------------------------------------------
__global__ __launch_bounds__(256, 1) void lstm_persistent() {
    extern __shared__ char smem[];
    uint32_t sb = smem_u32(smem);
    uint32_t mb = sb + SMEM_MB;
    const int tid = threadIdx.x, lane = tid & 31, wid = tid >> 5;
    const int wg = wid >> 2;               // K-group (0/1)
    const int wq = wid & 3;
    const int wm = wq & 1, wn = wq >> 1;   // 32x32 output quadrant
    const int ntile = blockIdx.x >> 1, mh = blockIdx.x & 1;
    const int p0 = ntile * 64, m0 = mh * 64;
    float* cs0 = (float*)(smem + SMEM_CS);
    float* cs1 = cs0 + 1024;
    for (int i = tid; i < 2048; i += 256) cs0[i] = 0.f;
    if (tid == 0) {
        for (int s = 0; s < NSTAGE; s++) MBARRIER_INIT(mb + s * 8, 1);
        FENCE_PROXY_ASYNC();
    }
    __syncthreads();

    const unsigned char* W0b = g_W0p + (size_t)ntile * NCH0 * 8192;
    const unsigned char* W1b = g_W1p + (size_t)ntile * NCH1 * 8192;
    const size_t mo = (size_t)mh * 8192;

    unsigned gc = 0, bar = 0;
    Job jb[2], jbn[2];

    auto setup_phase = [&](Job* J, int t) {
        const int pc = t & 1, pn = (t + 1) & 1;
        J[0].A0 = g_h0p[pc] + mo; J[0].A1 = g_h1p[pn] + mo;
        J[0].Wb = W1b; J[0].nst = NST1;
        J[0].biasp = g_b1p; J[0].cseg = cs1; J[0].hout = g_h1p[pc];
        J[1].A0 = g_h0p[pc] + mo;
        J[1].A1 = g_Xp + (size_t)(t + 1) * 8 * BLK + mo;
        J[1].Wb = W0b; J[1].nst = NST0;
        J[1].biasp = g_b0p; J[1].cseg = cs0; J[1].hout = g_h0p[pn];
    };

    // initial layer0(0): A=[h0[1](zeros); X(0)] -> h0[0]
    jb[0].A0 = g_h0p[1] + mo; jb[0].A1 = g_Xp + mo;
    jb[0].Wb = W0b; jb[0].nst = NST0;
    jb[0].biasp = g_b0p; jb[0].cseg = cs0; jb[0].hout = g_h0p[0];
    phase_exec(jb, 1, false, gc, smem, sb, mb, tid, wg, wm, wn, lane, m0, p0);

    setup_phase(jb, 0);
    if (tid == 0)
#pragma unroll
        for (int c = 0; c < NPRE; c++)
            issue_W_stage(jb, jb[0].nst, c, gc + c, sb, mb);
    grid_bar(++bar * NCTA);

    for (int t = 0; t < Tn - 1; t++) {
        phase_exec(jb, 2, true, gc, smem, sb, mb, tid, wg, wm, wn, lane, m0, p0);
        if (t + 1 < Tn - 1) {
            setup_phase(jbn, t + 1);
        } else {
            // final: layer1(255): A=[h0[1]; h1[0]] -> h1[1]
            jbn[0].A0 = g_h0p[1] + mo; jbn[0].A1 = g_h1p[0] + mo;
            jbn[0].Wb = W1b; jbn[0].nst = NST1;
            jbn[0].biasp = g_b1p; jbn[0].cseg = cs1; jbn[0].hout = g_h1p[1];
        }
        if (tid == 0)
#pragma unroll
            for (int c = 0; c < NPRE; c++)
                issue_W_stage(jbn, jbn[0].nst, c, gc + c, sb, mb);
        grid_bar(++bar * NCTA);
        jb[0] = jbn[0]; jb[1] = jbn[1];
    }

    phase_exec(jb, 1, true, gc, smem, sb, mb, tid, wg, wm, wn, lane, m0, p0);
}

// ---------------------------------------------------------------------------
// Final head: out[b][r] = elu(h1(255)[b] . W_br[r] + b_br[r])
// ---------------------------------------------------------------------------
__global__ void br_kernel(const float* __restrict__ Wbr,
                          const float* __restrict__ bbr,
                          float* __restrict__ out) {
    __shared__ float hs[Hn];
    const int b = blockIdx.x;
    for (int k = threadIdx.x; k < Hn; k += 256) {
        size_t off = (size_t)(k >> 6) * BLK + SWZ128(b * 128 + (k & 63) * 2);
        hs[k] = __half2float(*(const __half*)(g_h1p[1] + off));
    }
    __syncthreads();
    const int r = threadIdx.x;
    float acc = bbr[r];
    const float* w = Wbr + (size_t)r * Hn;
    for (int k = 0; k < Hn; k += 4) {
        float4 wv = *reinterpret_cast<const float4*>(w + k);
        float4 hv = *reinterpret_cast<const float4*>(&hs[k]);
        acc += wv.x * hv.x + wv.y * hv.y + wv.z * hv.z + wv.w * hv.w;
    }
    out[b * BRn + r] = acc > 0.f ? acc : expm1f(acc);
}

// ---------------------------------------------------------------------------
extern "C" void kernel_launch(void* const* d_in, const int* in_sizes, int n_in,
                              void* d_out, int out_size) {
    const float* X     = (const float*)d_in[0];
    const float* W_ih0 = (const float*)d_in[1];
    const float* W_hh0 = (const float*)d_in[2];
    const float* b_ih0 = (const float*)d_in[3];
    const float* b_hh0 = (const float*)d_in[4];
    const float* W_ih1 = (const float*)d_in[5];
    const float* W_hh1 = (const float*)d_in[6];
    const float* b_ih1 = (const float*)d_in[7];
    const float* b_hh1 = (const float*)d_in[8];
    const float* W_br  = (const float*)d_in[9];
    const float* b_br  = (const float*)d_in[10];
    float* out = (float*)d_out;

    cudaFuncSetAttribute(lstm_persistent, cudaFuncAttributeMaxDynamicSharedMemorySize,
                         SMEM_BYTES);

    pack_X_kernel<<<(Bn * Tn * DIN) / 256, 256>>>(X);
    pack_w0_kernel<<<((int)((size_t)G4 * 1536 / 256)), 256>>>(W_ih0, W_hh0);
    pack_w1_kernel<<<((int)((size_t)G4 * 2048 / 256)), 256>>>(W_ih1, W_hh1);
    pack_bias_kernel<<<G4 / 256, 256>>>(b_ih0, b_hh0, b_ih1, b_hh1);
    init_state_kernel<<<256, 256>>>();

    lstm_persistent<<<NCTA, 256, SMEM_BYTES>>>();

    br_kernel<<<Bn, 256>>>(W_br, b_br, out);
}